// round 1
// baseline (speedup 1.0000x reference)
#include <cuda_runtime.h>

#define NN 50000
#define EE 800000
#define EPSB 1e-5f

// ---------------- scratch (device globals: no allocation allowed) ----------------
__device__ __align__(256) float g_sum96[NN * 96];    // conv1 aggregated [x | ea]
__device__ __align__(256) float g_h1[NN * 128];
__device__ __align__(256) float g_h2[NN * 128];
__device__ __align__(256) float g_h3[NN * 128];
__device__ __align__(256) float g_aggA[NN * 128];
__device__ __align__(256) float g_aggB[NN * 128];
__device__ __align__(256) float g_z[NN * 64];
__device__ __align__(256) int   g_cnt[3 * NN];
__device__ __align__(256) float g_invc[3 * NN];
__device__ __align__(256) float g_WT1[96 * 128];
__device__ __align__(256) float g_WT2[256 * 128];
__device__ __align__(256) float g_WT3[256 * 128];
__device__ __align__(256) float g_WT4[192 * 64];

__device__ __forceinline__ void red4(float* p, float4 v) {
    asm volatile("red.global.add.v4.f32 [%0], {%1,%2,%3,%4};"
                 :: "l"(p), "f"(v.x), "f"(v.y), "f"(v.z), "f"(v.w) : "memory");
}

// ---------------- small utility kernels ----------------

// dst[k*M + m] = src[m*K + k]   (src is W [M,K] row-major; dst is W^T [K,M])
__global__ void transpose_k(const float* __restrict__ src, float* __restrict__ dst,
                            int M, int K) {
    int idx = blockIdx.x * blockDim.x + threadIdx.x;
    if (idx < M * K) {
        int m = idx / K;
        int k = idx - m * K;
        dst[k * M + m] = src[idx];
    }
}

// degree counts for the three edge lists (dst row = second row of [2,E])
__global__ void count_kernel(const int* __restrict__ e0, const int* __restrict__ e1,
                             const int* __restrict__ e2, int* __restrict__ cnt) {
    int i = blockIdx.x * blockDim.x + threadIdx.x;
    if (i < EE) {
        atomicAdd(&cnt[e0[EE + i]], 1);
    } else if (i < 2 * EE) {
        int j = i - EE;
        atomicAdd(&cnt[NN + e1[EE + j]], 1);
    } else if (i < 3 * EE) {
        int j = i - 2 * EE;
        atomicAdd(&cnt[2 * NN + e2[EE + j]], 1);
    }
}

__global__ void inv_kernel(const int* __restrict__ cnt, float* __restrict__ invc) {
    int i = blockIdx.x * blockDim.x + threadIdx.x;
    if (i < 3 * NN) {
        int c = cnt[i];
        invc[i] = (c > 0) ? (1.0f / (float)c) : 0.0f;
    }
}

// conv1 scatter: per edge, add x[src] (64f) and ea[e] (32f) into sum96[dst] (96f).
// one warp per edge; lanes 0..15 carry x float4s, lanes 16..23 carry ea float4s.
__global__ void scatter1_kernel(const float* __restrict__ x, const float* __restrict__ ea,
                                const int* __restrict__ ei, float* __restrict__ sum96) {
    int gt = blockIdx.x * blockDim.x + threadIdx.x;
    int e = gt >> 5;
    int lane = gt & 31;
    if (e >= EE) return;
    int src = ei[e];
    int dst = ei[EE + e];
    float* base = sum96 + (size_t)dst * 96;
    if (lane < 16) {
        float4 v = ((const float4*)x)[(size_t)src * 16 + lane];
        red4(base + lane * 4, v);
    } else if (lane < 24) {
        int l = lane - 16;
        float4 v = ((const float4*)ea)[(size_t)e * 8 + l];
        red4(base + 64 + l * 4, v);
    }
}

// SAGE scatter: per edge, add h[src] (128f) into agg[dst]. one warp per edge.
__global__ void scatterH_kernel(const float* __restrict__ h, const int* __restrict__ ei,
                                float* __restrict__ agg) {
    int gt = blockIdx.x * blockDim.x + threadIdx.x;
    int e = gt >> 5;
    int lane = gt & 31;
    if (e >= EE) return;
    int src = ei[e];
    int dst = ei[EE + e];
    float4 v = ((const float4*)h)[(size_t)src * 32 + lane];
    red4(agg + (size_t)dst * 128 + lane * 4, v);
}

// ---------------- fused GEMM ----------------
// out[N, M] = epilogue( [A0*diag(invc) | A1] @ BT + ... )
// A0: [N, K0] scaled per-row by invc (if invc != nullptr); A1: [N, K1] unscaled.
// BT: [(K0+K1), M] pre-transposed weights.
// mode 0: conv1  -> v = relu(acc + bias) * (deg>0);  v = relu(bn(v))
// mode 1: sage   -> v = acc + bias;                   v = relu(bn(v))
// mode 2: mlp    -> v = relu(acc + bias)
// Tile: BM=64, BN=64, BK=16; 256 threads; 4x4 micro-tile per thread.
__global__ void gemm_fused(const float* __restrict__ A0, int K0,
                           const float* __restrict__ A1, int K1,
                           const float* __restrict__ invc,
                           const float* __restrict__ BT, int M,
                           const float* __restrict__ bias,
                           const float* __restrict__ gamma, const float* __restrict__ beta,
                           const float* __restrict__ mean, const float* __restrict__ var,
                           float* __restrict__ out, int mode) {
    __shared__ float As[16][68];   // [k][m], padded
    __shared__ float Bs[16][64];   // [k][n]

    const int K = K0 + K1;
    int tid = threadIdx.x;
    int tx = tid & 15;          // n direction (4 cols each)
    int ty = tid >> 4;          // m direction (4 rows each)
    int brow = blockIdx.x * 64;
    int bcol = blockIdx.y * 64;

    // A-load mapping: each thread loads one float4 of a row slice
    int lrow = tid >> 2;            // 0..63
    int lkg  = (tid & 3) * 4;       // 0,4,8,12
    // B-load mapping
    int lk  = tid >> 4;             // 0..15
    int lng = (tid & 15) * 4;       // 0..60

    float acc[4][4];
#pragma unroll
    for (int i = 0; i < 4; i++)
#pragma unroll
        for (int j = 0; j < 4; j++) acc[i][j] = 0.0f;

    int arow = brow + lrow;
    float scale0 = 1.0f;
    if (invc != nullptr) scale0 = (arow < NN) ? invc[arow] : 0.0f;

    for (int kt = 0; kt < K; kt += 16) {
        float4 av = make_float4(0.f, 0.f, 0.f, 0.f);
        float sc = 1.0f;
        if (arow < NN) {
            if (kt < K0) {
                av = *(const float4*)(A0 + (size_t)arow * K0 + kt + lkg);
                sc = scale0;
            } else {
                av = *(const float4*)(A1 + (size_t)arow * K1 + (kt - K0) + lkg);
            }
        }
        As[lkg + 0][lrow] = av.x * sc;
        As[lkg + 1][lrow] = av.y * sc;
        As[lkg + 2][lrow] = av.z * sc;
        As[lkg + 3][lrow] = av.w * sc;

        *(float4*)&Bs[lk][lng] =
            *(const float4*)(BT + (size_t)(kt + lk) * M + bcol + lng);

        __syncthreads();
#pragma unroll
        for (int k = 0; k < 16; k++) {
            float a0 = As[k][ty * 4 + 0];
            float a1 = As[k][ty * 4 + 1];
            float a2 = As[k][ty * 4 + 2];
            float a3 = As[k][ty * 4 + 3];
            float4 b = *(const float4*)&Bs[k][tx * 4];
            acc[0][0] += a0 * b.x; acc[0][1] += a0 * b.y; acc[0][2] += a0 * b.z; acc[0][3] += a0 * b.w;
            acc[1][0] += a1 * b.x; acc[1][1] += a1 * b.y; acc[1][2] += a1 * b.z; acc[1][3] += a1 * b.w;
            acc[2][0] += a2 * b.x; acc[2][1] += a2 * b.y; acc[2][2] += a2 * b.z; acc[2][3] += a2 * b.w;
            acc[3][0] += a3 * b.x; acc[3][1] += a3 * b.y; acc[3][2] += a3 * b.z; acc[3][3] += a3 * b.w;
        }
        __syncthreads();
    }

#pragma unroll
    for (int i = 0; i < 4; i++) {
        int row = brow + ty * 4 + i;
        if (row >= NN) continue;
        float msk = 1.0f;
        if (mode == 0) msk = (invc[row] > 0.0f) ? 1.0f : 0.0f;
#pragma unroll
        for (int j = 0; j < 4; j++) {
            int col = bcol + tx * 4 + j;
            float v = acc[i][j] + bias[col];
            if (mode == 0) {
                v = fmaxf(v, 0.0f) * msk;
                v = gamma[col] * (v - mean[col]) * rsqrtf(var[col] + EPSB) + beta[col];
                v = fmaxf(v, 0.0f);
            } else if (mode == 1) {
                v = gamma[col] * (v - mean[col]) * rsqrtf(var[col] + EPSB) + beta[col];
                v = fmaxf(v, 0.0f);
            } else {
                v = fmaxf(v, 0.0f);
            }
            out[(size_t)row * M + col] = v;
        }
    }
}

// final: out[i] = b5 + dot(z[i, 0:64], W5)
__global__ void final_kernel(const float* __restrict__ z, const float* __restrict__ W5,
                             const float* __restrict__ b5, float* __restrict__ out) {
    int i = blockIdx.x * blockDim.x + threadIdx.x;
    if (i >= NN) return;
    const float4* zr = (const float4*)(z + (size_t)i * 64);
    const float4* wr = (const float4*)W5;
    float acc = 0.0f;
#pragma unroll
    for (int j = 0; j < 16; j++) {
        float4 a = zr[j];
        float4 w = wr[j];
        acc += a.x * w.x + a.y * w.y + a.z * w.z + a.w * w.w;
    }
    out[i] = acc + b5[0];
}

// ---------------- launch ----------------
extern "C" void kernel_launch(void* const* d_in, const int* in_sizes, int n_in,
                              void* d_out, int out_size) {
    const float* x   = (const float*)d_in[0];
    const int*   ei0 = (const int*)d_in[1];
    const int*   ei1 = (const int*)d_in[2];
    const int*   ei2 = (const int*)d_in[3];
    const float* ea  = (const float*)d_in[4];
    const float* W1  = (const float*)d_in[5];
    const float* b1  = (const float*)d_in[6];
    const float* g1  = (const float*)d_in[7];
    const float* be1 = (const float*)d_in[8];
    const float* m1  = (const float*)d_in[9];
    const float* v1  = (const float*)d_in[10];
    const float* Wl2 = (const float*)d_in[11];
    const float* bl2 = (const float*)d_in[12];
    const float* Wr2 = (const float*)d_in[13];
    const float* g2  = (const float*)d_in[14];
    const float* be2 = (const float*)d_in[15];
    const float* m2  = (const float*)d_in[16];
    const float* v2  = (const float*)d_in[17];
    const float* Wl3 = (const float*)d_in[18];
    const float* bl3 = (const float*)d_in[19];
    const float* Wr3 = (const float*)d_in[20];
    const float* g3  = (const float*)d_in[21];
    const float* be3 = (const float*)d_in[22];
    const float* m3  = (const float*)d_in[23];
    const float* v3  = (const float*)d_in[24];
    const float* W4  = (const float*)d_in[25];
    const float* b4  = (const float*)d_in[26];
    const float* W5  = (const float*)d_in[27];
    const float* b5  = (const float*)d_in[28];
    float* out = (float*)d_out;

    float *sum96, *h1, *h2, *h3, *aggA, *aggB, *z, *invc, *WT1, *WT2, *WT3, *WT4;
    int* cnt;
    cudaGetSymbolAddress((void**)&sum96, g_sum96);
    cudaGetSymbolAddress((void**)&h1, g_h1);
    cudaGetSymbolAddress((void**)&h2, g_h2);
    cudaGetSymbolAddress((void**)&h3, g_h3);
    cudaGetSymbolAddress((void**)&aggA, g_aggA);
    cudaGetSymbolAddress((void**)&aggB, g_aggB);
    cudaGetSymbolAddress((void**)&z, g_z);
    cudaGetSymbolAddress((void**)&cnt, g_cnt);
    cudaGetSymbolAddress((void**)&invc, g_invc);
    cudaGetSymbolAddress((void**)&WT1, g_WT1);
    cudaGetSymbolAddress((void**)&WT2, g_WT2);
    cudaGetSymbolAddress((void**)&WT3, g_WT3);
    cudaGetSymbolAddress((void**)&WT4, g_WT4);

    // zero accumulators + counts
    cudaMemsetAsync(cnt, 0, 3 * NN * sizeof(int), 0);
    cudaMemsetAsync(sum96, 0, (size_t)NN * 96 * sizeof(float), 0);
    cudaMemsetAsync(aggA, 0, (size_t)NN * 128 * sizeof(float), 0);
    cudaMemsetAsync(aggB, 0, (size_t)NN * 128 * sizeof(float), 0);

    // weight transposes (tiny)
    transpose_k<<<(128 * 96 + 255) / 256, 256>>>(W1, WT1, 128, 96);
    transpose_k<<<(128 * 128 + 255) / 256, 256>>>(Wl2, WT2, 128, 128);
    transpose_k<<<(128 * 128 + 255) / 256, 256>>>(Wr2, WT2 + 128 * 128, 128, 128);
    transpose_k<<<(128 * 128 + 255) / 256, 256>>>(Wl3, WT3, 128, 128);
    transpose_k<<<(128 * 128 + 255) / 256, 256>>>(Wr3, WT3 + 128 * 128, 128, 128);
    transpose_k<<<(64 * 192 + 255) / 256, 256>>>(W4, WT4, 64, 192);

    // degrees + reciprocals
    count_kernel<<<(3 * EE + 255) / 256, 256>>>(ei0, ei1, ei2, cnt);
    inv_kernel<<<(3 * NN + 255) / 256, 256>>>(cnt, invc);

    const int sblocks = (int)(((long long)EE * 32 + 255) / 256);
    dim3 gemm_grid((NN + 63) / 64, 2);
    dim3 mlp_grid((NN + 63) / 64, 1);

    // conv1
    scatter1_kernel<<<sblocks, 256>>>(x, ea, ei0, sum96);
    gemm_fused<<<gemm_grid, 256>>>(sum96, 96, nullptr, 0, invc,
                                   WT1, 128, b1, g1, be1, m1, v1, h1, 0);
    // conv2 (SAGE)
    scatterH_kernel<<<sblocks, 256>>>(h1, ei1, aggA);
    gemm_fused<<<gemm_grid, 256>>>(aggA, 128, h1, 128, invc + NN,
                                   WT2, 128, bl2, g2, be2, m2, v2, h2, 1);
    // conv3 (SAGE)
    scatterH_kernel<<<sblocks, 256>>>(h2, ei2, aggB);
    gemm_fused<<<gemm_grid, 256>>>(aggB, 128, h2, 128, invc + 2 * NN,
                                   WT3, 128, bl3, g3, be3, m3, v3, h3, 1);
    // readout MLP
    gemm_fused<<<mlp_grid, 256>>>(h3, 128, x, 64, nullptr,
                                  WT4, 64, b4, nullptr, nullptr, nullptr, nullptr, z, 2);
    final_kernel<<<(NN + 255) / 256, 256>>>(z, W5, b5, out);
}

// round 2
// speedup vs baseline: 1.2392x; 1.2392x over previous
#include <cuda_runtime.h>

#define NN 50000
#define EE 800000
#define EPSB 1e-5f

// ---------------- scratch (device globals) ----------------
__device__ __align__(256) float g_sum96[NN * 96];
__device__ __align__(256) float g_h1[NN * 128];
__device__ __align__(256) float g_h2[NN * 128];
__device__ __align__(256) float g_h3[NN * 128];
__device__ __align__(256) float g_aggA[NN * 128];
__device__ __align__(256) float g_aggB[NN * 128];
__device__ __align__(256) float g_z[NN * 64];
__device__ __align__(256) int   g_cnt[3 * NN];
__device__ __align__(256) float g_invc[3 * NN];
__device__ __align__(256) int   g_rowptr[3 * (NN + 1)];
__device__ __align__(256) int   g_cursor[3 * NN];
__device__ __align__(256) int   g_col[3 * EE];
__device__ __align__(256) int   g_eid0[EE];
__device__ __align__(256) float g_WT1[96 * 128];
__device__ __align__(256) float g_WT2[256 * 128];
__device__ __align__(256) float g_WT3[256 * 128];
__device__ __align__(256) float g_WT4[192 * 64];

// ---------------- utility kernels ----------------
__global__ void transpose_k(const float* __restrict__ src, float* __restrict__ dst,
                            int M, int K) {
    int idx = blockIdx.x * blockDim.x + threadIdx.x;
    if (idx < M * K) {
        int m = idx / K;
        int k = idx - m * K;
        dst[k * M + m] = src[idx];
    }
}

__global__ void count_kernel(const int* __restrict__ e0, const int* __restrict__ e1,
                             const int* __restrict__ e2, int* __restrict__ cnt) {
    int i = blockIdx.x * blockDim.x + threadIdx.x;
    if (i < EE) {
        atomicAdd(&cnt[e0[EE + i]], 1);
    } else if (i < 2 * EE) {
        atomicAdd(&cnt[NN + e1[EE + (i - EE)]], 1);
    } else if (i < 3 * EE) {
        atomicAdd(&cnt[2 * NN + e2[EE + (i - 2 * EE)]], 1);
    }
}

__global__ void inv_kernel(const int* __restrict__ cnt, float* __restrict__ invc) {
    int i = blockIdx.x * blockDim.x + threadIdx.x;
    if (i < 3 * NN) {
        int c = cnt[i];
        invc[i] = (c > 0) ? (1.0f / (float)c) : 0.0f;
    }
}

// exclusive scan of one list's counts -> rowptr, cursor. 3 blocks, 1024 threads.
__global__ void scan_kernel(const int* __restrict__ cnt, int* __restrict__ rowptr,
                            int* __restrict__ cursor) {
    int L = blockIdx.x;
    const int* c = cnt + L * NN;
    int* rp = rowptr + L * (NN + 1);
    int* cur = cursor + L * NN;
    __shared__ int sh[1024];
    int t = threadIdx.x;
    const int per = (NN + 1023) / 1024;
    int start = t * per;
    int end = min(start + per, NN);
    int s = 0;
    for (int i = start; i < end; i++) s += c[i];
    sh[t] = s;
    __syncthreads();
#pragma unroll
    for (int off = 1; off < 1024; off <<= 1) {
        int v = (t >= off) ? sh[t - off] : 0;
        __syncthreads();
        sh[t] += v;
        __syncthreads();
    }
    int run = sh[t] - s;  // exclusive prefix
    for (int i = start; i < end; i++) {
        rp[i] = run;
        cur[i] = run;
        run += c[i];
    }
    if (end == NN && start < NN) rp[NN] = run;
}

// fill CSR column (and optional edge-id) array
__global__ void fill_kernel(const int* __restrict__ ei, int* __restrict__ cursor,
                            int* __restrict__ col, int* __restrict__ eid) {
    int e = blockIdx.x * blockDim.x + threadIdx.x;
    if (e >= EE) return;
    int src = ei[e];
    int dst = ei[EE + e];
    int pos = atomicAdd(&cursor[dst], 1);
    col[pos] = src;
    if (eid) eid[pos] = e;
}

// conv1 aggregate: warp per dst node; sum96[d] = invc[d] * sum_e [x[src] | ea[e]]
__global__ void agg1_kernel(const float* __restrict__ x, const float* __restrict__ ea,
                            const int* __restrict__ rowptr, const int* __restrict__ col,
                            const int* __restrict__ eid, const float* __restrict__ invc,
                            float* __restrict__ sum96) {
    int warp = (blockIdx.x * blockDim.x + threadIdx.x) >> 5;
    int lane = threadIdx.x & 31;
    if (warp >= NN) return;
    int s = rowptr[warp], e = rowptr[warp + 1];
    float a0 = 0.f, a1 = 0.f, a2 = 0.f;
    for (int p = s; p < e; p++) {
        int src = col[p];
        int id = eid[p];
        a0 += x[(size_t)src * 64 + lane];
        a1 += x[(size_t)src * 64 + 32 + lane];
        a2 += ea[(size_t)id * 32 + lane];
    }
    float ic = invc[warp];
    float* o = sum96 + (size_t)warp * 96;
    o[lane] = a0 * ic;
    o[32 + lane] = a1 * ic;
    o[64 + lane] = a2 * ic;
}

// SAGE aggregate: warp per dst node; agg[d] = invc[d] * sum h[src]
__global__ void aggH_kernel(const float* __restrict__ h, const int* __restrict__ rowptr,
                            const int* __restrict__ col, const float* __restrict__ invc,
                            float* __restrict__ agg) {
    int warp = (blockIdx.x * blockDim.x + threadIdx.x) >> 5;
    int lane = threadIdx.x & 31;
    if (warp >= NN) return;
    int s = rowptr[warp], e = rowptr[warp + 1];
    float a0 = 0.f, a1 = 0.f, a2 = 0.f, a3 = 0.f;
    for (int p = s; p < e; p++) {
        const float* r = h + (size_t)col[p] * 128;
        a0 += r[lane];
        a1 += r[32 + lane];
        a2 += r[64 + lane];
        a3 += r[96 + lane];
    }
    float ic = invc[warp];
    float* o = agg + (size_t)warp * 128;
    o[lane] = a0 * ic;
    o[32 + lane] = a1 * ic;
    o[64 + lane] = a2 * ic;
    o[96 + lane] = a3 * ic;
}

// ---------------- fused GEMM ----------------
// out[N, M] = epi( [A0 | A1] @ BT + bias )
// BM=128, BN=64, BK=16; 256 threads; 8x4 micro-tile; register double-buffered loads.
// mode 0: conv1 -> relu(acc+bias)*mask(deg>0) -> relu(bn)
// mode 1: sage  -> acc+bias -> relu(bn)
// mode 2: mlp   -> relu(acc+bias)
__global__ __launch_bounds__(256, 3)
void gemm_fused(const float* __restrict__ A0, int K0,
                const float* __restrict__ A1, int K1,
                const float* __restrict__ invc,
                const float* __restrict__ BT, int M,
                const float* __restrict__ bias,
                const float* __restrict__ gamma, const float* __restrict__ beta,
                const float* __restrict__ mean, const float* __restrict__ var,
                float* __restrict__ out, int mode) {
    __shared__ float As[16][136];  // [k][m], padded: 136*4 = 544 B (16B aligned)
    __shared__ float Bs[16][64];

    const int K = K0 + K1;
    const int nkt = K >> 4;
    int tid = threadIdx.x;
    int tx = tid & 15;   // col group: 4 cols
    int ty = tid >> 4;   // row group: 8 rows
    int brow = blockIdx.x * 128;
    int bcol = blockIdx.y * 64;

    // A-load map: 512 float4 per tile; thread handles idx = tid, tid+256
    int arow0 = brow + (tid >> 2);
    int arow1 = brow + ((tid + 256) >> 2);
    int akq = (tid & 3) * 4;
    // B-load map: 256 float4; k = tid>>4, n = (tid&15)*4
    int blk = tid >> 4;
    int bln = (tid & 15) * 4;

    float acc[8][4];
#pragma unroll
    for (int i = 0; i < 8; i++)
#pragma unroll
        for (int j = 0; j < 4; j++) acc[i][j] = 0.0f;

    float4 ra0, ra1, rb;

    // prologue: load tile 0
    {
        int kg = akq;
        ra0 = make_float4(0.f, 0.f, 0.f, 0.f);
        ra1 = make_float4(0.f, 0.f, 0.f, 0.f);
        if (arow0 < NN) {
            ra0 = (kg < K0) ? *(const float4*)(A0 + (size_t)arow0 * K0 + kg)
                            : *(const float4*)(A1 + (size_t)arow0 * K1 + (kg - K0));
        }
        if (arow1 < NN) {
            ra1 = (kg < K0) ? *(const float4*)(A0 + (size_t)arow1 * K0 + kg)
                            : *(const float4*)(A1 + (size_t)arow1 * K1 + (kg - K0));
        }
        rb = *(const float4*)(BT + (size_t)blk * M + bcol + bln);
    }

    for (int t = 0; t < nkt; t++) {
        // store current regs into smem
        {
            int r0 = arow0 - brow, r1 = arow1 - brow;
            As[akq + 0][r0] = ra0.x; As[akq + 1][r0] = ra0.y;
            As[akq + 2][r0] = ra0.z; As[akq + 3][r0] = ra0.w;
            As[akq + 0][r1] = ra1.x; As[akq + 1][r1] = ra1.y;
            As[akq + 2][r1] = ra1.z; As[akq + 3][r1] = ra1.w;
            *(float4*)&Bs[blk][bln] = rb;
        }
        __syncthreads();

        // prefetch next tile
        if (t + 1 < nkt) {
            int kt = (t + 1) << 4;
            int kg = kt + akq;
            ra0 = make_float4(0.f, 0.f, 0.f, 0.f);
            ra1 = make_float4(0.f, 0.f, 0.f, 0.f);
            if (arow0 < NN) {
                ra0 = (kg < K0) ? *(const float4*)(A0 + (size_t)arow0 * K0 + kg)
                                : *(const float4*)(A1 + (size_t)arow0 * K1 + (kg - K0));
            }
            if (arow1 < NN) {
                ra1 = (kg < K0) ? *(const float4*)(A0 + (size_t)arow1 * K0 + kg)
                                : *(const float4*)(A1 + (size_t)arow1 * K1 + (kg - K0));
            }
            rb = *(const float4*)(BT + (size_t)(kt + blk) * M + bcol + bln);
        }

        // compute
#pragma unroll
        for (int k = 0; k < 16; k++) {
            float4 a0 = *(const float4*)&As[k][ty * 8];
            float4 a1 = *(const float4*)&As[k][ty * 8 + 4];
            float4 b = *(const float4*)&Bs[k][tx * 4];
            acc[0][0] += a0.x * b.x; acc[0][1] += a0.x * b.y; acc[0][2] += a0.x * b.z; acc[0][3] += a0.x * b.w;
            acc[1][0] += a0.y * b.x; acc[1][1] += a0.y * b.y; acc[1][2] += a0.y * b.z; acc[1][3] += a0.y * b.w;
            acc[2][0] += a0.z * b.x; acc[2][1] += a0.z * b.y; acc[2][2] += a0.z * b.z; acc[2][3] += a0.z * b.w;
            acc[3][0] += a0.w * b.x; acc[3][1] += a0.w * b.y; acc[3][2] += a0.w * b.z; acc[3][3] += a0.w * b.w;
            acc[4][0] += a1.x * b.x; acc[4][1] += a1.x * b.y; acc[4][2] += a1.x * b.z; acc[4][3] += a1.x * b.w;
            acc[5][0] += a1.y * b.x; acc[5][1] += a1.y * b.y; acc[5][2] += a1.y * b.z; acc[5][3] += a1.y * b.w;
            acc[6][0] += a1.z * b.x; acc[6][1] += a1.z * b.y; acc[6][2] += a1.z * b.z; acc[6][3] += a1.z * b.w;
            acc[7][0] += a1.w * b.x; acc[7][1] += a1.w * b.y; acc[7][2] += a1.w * b.z; acc[7][3] += a1.w * b.w;
        }
        __syncthreads();
    }

    // epilogue
#pragma unroll
    for (int i = 0; i < 8; i++) {
        int row = brow + ty * 8 + i;
        if (row >= NN) continue;
        float msk = 1.0f;
        if (mode == 0) msk = (invc[row] > 0.0f) ? 1.0f : 0.0f;
#pragma unroll
        for (int j = 0; j < 4; j++) {
            int col = bcol + tx * 4 + j;
            float v = acc[i][j] + bias[col];
            if (mode == 0) {
                v = fmaxf(v, 0.0f) * msk;
                v = gamma[col] * (v - mean[col]) * rsqrtf(var[col] + EPSB) + beta[col];
                v = fmaxf(v, 0.0f);
            } else if (mode == 1) {
                v = gamma[col] * (v - mean[col]) * rsqrtf(var[col] + EPSB) + beta[col];
                v = fmaxf(v, 0.0f);
            } else {
                v = fmaxf(v, 0.0f);
            }
            out[(size_t)row * M + col] = v;
        }
    }
}

// final: out[i] = b5 + dot(z[i, :64], W5)
__global__ void final_kernel(const float* __restrict__ z, const float* __restrict__ W5,
                             const float* __restrict__ b5, float* __restrict__ out) {
    int i = blockIdx.x * blockDim.x + threadIdx.x;
    if (i >= NN) return;
    const float4* zr = (const float4*)(z + (size_t)i * 64);
    const float4* wr = (const float4*)W5;
    float acc = 0.0f;
#pragma unroll
    for (int j = 0; j < 16; j++) {
        float4 a = zr[j];
        float4 w = wr[j];
        acc += a.x * w.x + a.y * w.y + a.z * w.z + a.w * w.w;
    }
    out[i] = acc + b5[0];
}

// ---------------- launch ----------------
extern "C" void kernel_launch(void* const* d_in, const int* in_sizes, int n_in,
                              void* d_out, int out_size) {
    const float* x   = (const float*)d_in[0];
    const int*   ei0 = (const int*)d_in[1];
    const int*   ei1 = (const int*)d_in[2];
    const int*   ei2 = (const int*)d_in[3];
    const float* ea  = (const float*)d_in[4];
    const float* W1  = (const float*)d_in[5];
    const float* b1  = (const float*)d_in[6];
    const float* g1  = (const float*)d_in[7];
    const float* be1 = (const float*)d_in[8];
    const float* m1  = (const float*)d_in[9];
    const float* v1  = (const float*)d_in[10];
    const float* Wl2 = (const float*)d_in[11];
    const float* bl2 = (const float*)d_in[12];
    const float* Wr2 = (const float*)d_in[13];
    const float* g2  = (const float*)d_in[14];
    const float* be2 = (const float*)d_in[15];
    const float* m2  = (const float*)d_in[16];
    const float* v2  = (const float*)d_in[17];
    const float* Wl3 = (const float*)d_in[18];
    const float* bl3 = (const float*)d_in[19];
    const float* Wr3 = (const float*)d_in[20];
    const float* g3  = (const float*)d_in[21];
    const float* be3 = (const float*)d_in[22];
    const float* m3  = (const float*)d_in[23];
    const float* v3  = (const float*)d_in[24];
    const float* W4  = (const float*)d_in[25];
    const float* b4  = (const float*)d_in[26];
    const float* W5  = (const float*)d_in[27];
    const float* b5  = (const float*)d_in[28];
    float* out = (float*)d_out;

    float *sum96, *h1, *h2, *h3, *aggA, *aggB, *z, *invc, *WT1, *WT2, *WT3, *WT4;
    int *cnt, *rowptr, *cursor, *colA, *eid0;
    cudaGetSymbolAddress((void**)&sum96, g_sum96);
    cudaGetSymbolAddress((void**)&h1, g_h1);
    cudaGetSymbolAddress((void**)&h2, g_h2);
    cudaGetSymbolAddress((void**)&h3, g_h3);
    cudaGetSymbolAddress((void**)&aggA, g_aggA);
    cudaGetSymbolAddress((void**)&aggB, g_aggB);
    cudaGetSymbolAddress((void**)&z, g_z);
    cudaGetSymbolAddress((void**)&cnt, g_cnt);
    cudaGetSymbolAddress((void**)&invc, g_invc);
    cudaGetSymbolAddress((void**)&rowptr, g_rowptr);
    cudaGetSymbolAddress((void**)&cursor, g_cursor);
    cudaGetSymbolAddress((void**)&colA, g_col);
    cudaGetSymbolAddress((void**)&eid0, g_eid0);
    cudaGetSymbolAddress((void**)&WT1, g_WT1);
    cudaGetSymbolAddress((void**)&WT2, g_WT2);
    cudaGetSymbolAddress((void**)&WT3, g_WT3);
    cudaGetSymbolAddress((void**)&WT4, g_WT4);

    cudaMemsetAsync(cnt, 0, 3 * NN * sizeof(int), 0);

    // weight transposes (tiny)
    transpose_k<<<(128 * 96 + 255) / 256, 256>>>(W1, WT1, 128, 96);
    transpose_k<<<(128 * 128 + 255) / 256, 256>>>(Wl2, WT2, 128, 128);
    transpose_k<<<(128 * 128 + 255) / 256, 256>>>(Wr2, WT2 + 128 * 128, 128, 128);
    transpose_k<<<(128 * 128 + 255) / 256, 256>>>(Wl3, WT3, 128, 128);
    transpose_k<<<(128 * 128 + 255) / 256, 256>>>(Wr3, WT3 + 128 * 128, 128, 128);
    transpose_k<<<(64 * 192 + 255) / 256, 256>>>(W4, WT4, 64, 192);

    // CSR build for all three edge lists
    count_kernel<<<(3 * EE + 255) / 256, 256>>>(ei0, ei1, ei2, cnt);
    inv_kernel<<<(3 * NN + 255) / 256, 256>>>(cnt, invc);
    scan_kernel<<<3, 1024>>>(cnt, rowptr, cursor);
    fill_kernel<<<(EE + 255) / 256, 256>>>(ei0, cursor, colA, eid0);
    fill_kernel<<<(EE + 255) / 256, 256>>>(ei1, cursor + NN, colA + EE, nullptr);
    fill_kernel<<<(EE + 255) / 256, 256>>>(ei2, cursor + 2 * NN, colA + 2 * EE, nullptr);

    const int agg_grid = (NN + 7) / 8;  // 8 warps per 256-thread block
    dim3 gemm_grid((NN + 127) / 128, 2);
    dim3 mlp_grid((NN + 127) / 128, 1);

    // conv1
    agg1_kernel<<<agg_grid, 256>>>(x, ea, rowptr, colA, eid0, invc, sum96);
    gemm_fused<<<gemm_grid, 256>>>(sum96, 96, nullptr, 0, invc,
                                   WT1, 128, b1, g1, be1, m1, v1, h1, 0);
    // conv2 (SAGE)
    aggH_kernel<<<agg_grid, 256>>>(h1, rowptr + (NN + 1), colA + EE, invc + NN, aggA);
    gemm_fused<<<gemm_grid, 256>>>(aggA, 128, h1, 128, nullptr,
                                   WT2, 128, bl2, g2, be2, m2, v2, h2, 1);
    // conv3 (SAGE)
    aggH_kernel<<<agg_grid, 256>>>(h2, rowptr + 2 * (NN + 1), colA + 2 * EE,
                                   invc + 2 * NN, aggB);
    gemm_fused<<<gemm_grid, 256>>>(aggB, 128, h2, 128, nullptr,
                                   WT3, 128, bl3, g3, be3, m3, v3, h3, 1);
    // readout MLP
    gemm_fused<<<mlp_grid, 256>>>(h3, 128, x, 64, nullptr,
                                  WT4, 64, b4, nullptr, nullptr, nullptr, nullptr, z, 2);
    final_kernel<<<(NN + 255) / 256, 256>>>(z, W5, b5, out);
}

// round 4
// speedup vs baseline: 1.7067x; 1.3773x over previous
#include <cuda_runtime.h>
#include <cuda_bf16.h>

#define NN 50000
#define EE 800000
#define EPSB 1e-5f

// ==================== device scratch (no allocation allowed) ====================
__device__ __align__(256) unsigned int g_a1h[NN * 64], g_a1l[NN * 64];
__device__ __align__(256) unsigned int g_aggh[NN * 64], g_aggl[NN * 64];
__device__ __align__(256) unsigned int g_h1h[NN * 64], g_h1l[NN * 64];
__device__ __align__(256) unsigned int g_h2h[NN * 64], g_h2l[NN * 64];
__device__ __align__(256) unsigned int g_h3h[NN * 64], g_h3l[NN * 64];
__device__ __align__(256) unsigned int g_xh[NN * 32], g_xl[NN * 32];
__device__ __align__(256) float g_z[NN * 64];
__device__ __align__(256) int   g_cnt[3 * NN];
__device__ __align__(256) float g_invc[3 * NN];
__device__ __align__(256) int   g_rowptr[3 * (NN + 1)];
__device__ __align__(256) int   g_cursor[3 * NN];
__device__ __align__(256) int   g_col[3 * EE];
__device__ __align__(256) int   g_eid0[EE];
// B images: row-major bf16 [NCOL][2K]  (cols 0..K-1 = hi split, K..2K-1 = lo split)
__device__ __align__(256) unsigned short g_B1[128 * 256];
__device__ __align__(256) unsigned short g_B2[128 * 512];
__device__ __align__(256) unsigned short g_B3[128 * 512];
__device__ __align__(256) unsigned short g_B4[64 * 384];

// ==================== helpers ====================
__device__ __forceinline__ unsigned int smem_u32(const void* p) {
    unsigned int a;
    asm("{ .reg .u64 t; cvta.to.shared.u64 t, %1; cvt.u32.u64 %0, t; }" : "=r"(a) : "l"(p));
    return a;
}
__device__ __forceinline__ void cp_async16(unsigned int saddr, const void* gaddr) {
    asm volatile("cp.async.cg.shared.global [%0], [%1], 16;" :: "r"(saddr), "l"(gaddr));
}
__device__ __forceinline__ void ldsm_x4(unsigned int* r, unsigned int addr) {
    asm volatile("ldmatrix.sync.aligned.m8n8.x4.shared.b16 {%0,%1,%2,%3}, [%4];"
                 : "=r"(r[0]), "=r"(r[1]), "=r"(r[2]), "=r"(r[3]) : "r"(addr));
}
__device__ __forceinline__ void mma16816(float* d, const unsigned int* a,
                                         unsigned int b0, unsigned int b1) {
    asm volatile("mma.sync.aligned.m16n8k16.row.col.f32.bf16.bf16.f32 "
                 "{%0,%1,%2,%3}, {%4,%5,%6,%7}, {%8,%9}, {%0,%1,%2,%3};"
                 : "+f"(d[0]), "+f"(d[1]), "+f"(d[2]), "+f"(d[3])
                 : "r"(a[0]), "r"(a[1]), "r"(a[2]), "r"(a[3]), "r"(b0), "r"(b1));
}
__device__ __forceinline__ unsigned short f2b(float v) {
    return __bfloat16_as_ushort(__float2bfloat16(v));
}
__device__ __forceinline__ float b2f(unsigned short u) {
    return __bfloat162float(__ushort_as_bfloat16(u));
}
__device__ __forceinline__ void split2(float v0, float v1, unsigned int& ph, unsigned int& pl) {
    unsigned short h0 = f2b(v0), h1 = f2b(v1);
    unsigned short l0 = f2b(v0 - b2f(h0)), l1 = f2b(v1 - b2f(h1));
    ph = (unsigned int)h0 | ((unsigned int)h1 << 16);
    pl = (unsigned int)l0 | ((unsigned int)l1 << 16);
}
__device__ __forceinline__ float plo(unsigned int u) { return b2f((unsigned short)(u & 0xFFFF)); }
__device__ __forceinline__ float phi(unsigned int u) { return b2f((unsigned short)(u >> 16)); }

// ==================== CSR build kernels ====================
__global__ void count_kernel(const int* __restrict__ e0, const int* __restrict__ e1,
                             const int* __restrict__ e2, int* __restrict__ cnt) {
    int i = blockIdx.x * blockDim.x + threadIdx.x;
    if (i < EE) atomicAdd(&cnt[e0[EE + i]], 1);
    else if (i < 2 * EE) atomicAdd(&cnt[NN + e1[EE + (i - EE)]], 1);
    else if (i < 3 * EE) atomicAdd(&cnt[2 * NN + e2[EE + (i - 2 * EE)]], 1);
}
__global__ void inv_kernel(const int* __restrict__ cnt, float* __restrict__ invc) {
    int i = blockIdx.x * blockDim.x + threadIdx.x;
    if (i < 3 * NN) {
        int c = cnt[i];
        invc[i] = (c > 0) ? (1.0f / (float)c) : 0.0f;
    }
}
__global__ void scan_kernel(const int* __restrict__ cnt, int* __restrict__ rowptr,
                            int* __restrict__ cursor) {
    int L = blockIdx.x;
    const int* c = cnt + L * NN;
    int* rp = rowptr + L * (NN + 1);
    int* cur = cursor + L * NN;
    __shared__ int sh[1024];
    int t = threadIdx.x;
    const int per = (NN + 1023) / 1024;
    int start = t * per;
    int end = min(start + per, NN);
    int s = 0;
    for (int i = start; i < end; i++) s += c[i];
    sh[t] = s;
    __syncthreads();
#pragma unroll
    for (int off = 1; off < 1024; off <<= 1) {
        int v = (t >= off) ? sh[t - off] : 0;
        __syncthreads();
        sh[t] += v;
        __syncthreads();
    }
    int run = sh[t] - s;
    for (int i = start; i < end; i++) {
        rp[i] = run;
        cur[i] = run;
        run += c[i];
    }
    if (end == NN && start < NN) rp[NN] = run;
}
__global__ void fill_kernel(const int* __restrict__ ei, int* __restrict__ cursor,
                            int* __restrict__ col, int* __restrict__ eid) {
    int e = blockIdx.x * blockDim.x + threadIdx.x;
    if (e >= EE) return;
    int src = ei[e];
    int dst = ei[EE + e];
    int pos = atomicAdd(&cursor[dst], 1);
    col[pos] = src;
    if (eid) eid[pos] = e;
}

// ==================== prep kernels ====================
// Weight -> bf16 hi/lo image, row-major [N][2K]. W = [Wa | Wb] along K, zero-padded.
__global__ void prep_B(const float* __restrict__ Wa, int Ka,
                       const float* __restrict__ Wb, int Kb,
                       int N, int K, unsigned short* __restrict__ img) {
    int idx = blockIdx.x * blockDim.x + threadIdx.x;
    if (idx >= N * K) return;
    int n = idx / K, k = idx - n * K;
    float w = 0.0f;
    if (k < Ka) w = Wa[n * Ka + k];
    else if (Wb != nullptr && (k - Ka) < Kb) w = Wb[n * Kb + (k - Ka)];
    unsigned short hb = f2b(w);
    unsigned short lb = f2b(w - b2f(hb));
    img[(size_t)n * 2 * K + k] = hb;
    img[(size_t)n * 2 * K + K + k] = lb;
}
// x (fp32 [NN,64]) -> packed bf16 hi/lo ([NN,32] words)
__global__ void prep_x(const float* __restrict__ x, unsigned int* __restrict__ xh,
                       unsigned int* __restrict__ xl) {
    int idx = blockIdx.x * blockDim.x + threadIdx.x;
    if (idx >= NN * 32) return;
    int i = idx >> 5, j = idx & 31;
    float2 v = *(const float2*)(x + (size_t)i * 64 + 2 * j);
    unsigned int ph, pl;
    split2(v.x, v.y, ph, pl);
    xh[idx] = ph;
    xl[idx] = pl;
}

// ==================== aggregation kernels ====================
// conv1: mean over [x_j | ea_e], out padded to 128 bf16 (64 words) hi/lo
__global__ void agg1_kernel(const float* __restrict__ x, const float* __restrict__ ea,
                            const int* __restrict__ rowptr, const int* __restrict__ col,
                            const int* __restrict__ eid, const float* __restrict__ invc,
                            unsigned int* __restrict__ ah, unsigned int* __restrict__ al) {
    int warp = (blockIdx.x * blockDim.x + threadIdx.x) >> 5;
    int lane = threadIdx.x & 31;
    if (warp >= NN) return;
    int s = rowptr[warp], e = rowptr[warp + 1];
    float ax0 = 0.f, ax1 = 0.f, ae0 = 0.f, ae1 = 0.f;
    for (int p = s; p < e; p++) {
        int src = col[p];
        float2 xv = *(const float2*)(x + (size_t)src * 64 + 2 * lane);
        ax0 += xv.x; ax1 += xv.y;
        if (lane < 16) {
            int id = eid[p];
            float2 ev = *(const float2*)(ea + (size_t)id * 32 + 2 * lane);
            ae0 += ev.x; ae1 += ev.y;
        }
    }
    float ic = invc[warp];
    unsigned int ph, pl;
    split2(ax0 * ic, ax1 * ic, ph, pl);
    ah[(size_t)warp * 64 + lane] = ph;
    al[(size_t)warp * 64 + lane] = pl;
    if (lane < 16) split2(ae0 * ic, ae1 * ic, ph, pl);
    else { ph = 0; pl = 0; }
    ah[(size_t)warp * 64 + 32 + lane] = ph;
    al[(size_t)warp * 64 + 32 + lane] = pl;
}

// SAGE mean over packed-bf16 h
__global__ void aggH_kernel(const unsigned int* __restrict__ hh, const unsigned int* __restrict__ hl,
                            const int* __restrict__ rowptr, const int* __restrict__ col,
                            const float* __restrict__ invc,
                            unsigned int* __restrict__ oh, unsigned int* __restrict__ ol) {
    int warp = (blockIdx.x * blockDim.x + threadIdx.x) >> 5;
    int lane = threadIdx.x & 31;
    if (warp >= NN) return;
    int s = rowptr[warp], e = rowptr[warp + 1];
    float a0 = 0.f, a1 = 0.f, a2 = 0.f, a3 = 0.f;
    for (int p = s; p < e; p++) {
        size_t base = (size_t)col[p] * 64;
        unsigned int u0 = hh[base + lane];
        unsigned int u1 = hh[base + 32 + lane];
        unsigned int w0 = hl[base + lane];
        unsigned int w1 = hl[base + 32 + lane];
        a0 += plo(u0) + plo(w0);
        a1 += phi(u0) + phi(w0);
        a2 += plo(u1) + plo(w1);
        a3 += phi(u1) + phi(w1);
    }
    float ic = invc[warp];
    unsigned int ph, pl;
    split2(a0 * ic, a1 * ic, ph, pl);
    oh[(size_t)warp * 64 + lane] = ph;
    ol[(size_t)warp * 64 + lane] = pl;
    split2(a2 * ic, a3 * ic, ph, pl);
    oh[(size_t)warp * 64 + 32 + lane] = ph;
    ol[(size_t)warp * 64 + 32 + lane] = pl;
}

// ==================== warp-MMA GEMM (split-bf16 fp32 emulation) ====================
// D[128, NCOL] = [A0|A1] @ W^T via 3 bf16 products: Ah*Wh + Ah*Wl + Al*Wh.
// A: bf16 row-major (hi/lo arrays). B image: [NCOL][2K] bf16 (hi | lo).
// 256 threads = 8 warps (4 M x 2 N). Warp tile 32 x NCOL/2. k-chunks of 64, cp.async 2-stage.
// MODE 0: conv1 (relu+mask -> bn -> relu, pack bf16 hi/lo out)
// MODE 1: sage  (bn -> relu, pack out)
// MODE 2: mlp   (relu, f32 out)
template <int K0, int K1, int NCOL, int MODE>
__global__ __launch_bounds__(256, 2)
void gemm_mma(const unsigned short* __restrict__ A0h, const unsigned short* __restrict__ A0l,
              const unsigned short* __restrict__ A1h, const unsigned short* __restrict__ A1l,
              const unsigned short* __restrict__ Bp,
              const float* __restrict__ bias,
              const float* __restrict__ gamma, const float* __restrict__ beta,
              const float* __restrict__ mean, const float* __restrict__ var,
              const float* __restrict__ invc,
              unsigned int* __restrict__ outHi, unsigned int* __restrict__ outLo,
              float* __restrict__ outF) {
    constexpr int K = K0 + K1;
    constexpr int NK64 = K / 64;
    constexpr int NCHUNK = 3 * NK64;
    constexpr int ABYTES = 128 * 128;   // 128 rows x 64 bf16
    constexpr int BBYTES = NCOL * 128;
    constexpr int STAGE = ABYTES + BBYTES;
    constexpr int WNC = NCOL / 2;       // warp N extent
    constexpr int NI = WNC / 8;         // n8 tiles per warp

    extern __shared__ char smem[];
    const unsigned int sbase = smem_u32(smem);

    const int tid = threadIdx.x;
    const int lane = tid & 31;
    const int warp = tid >> 5;
    const int wr = warp & 3;
    const int wc = warp >> 2;
    const int brow = blockIdx.x * 128;

    const int lane16 = lane & 15;
    const int lhalf = lane >> 4;
    const int swz = lane16 & 7;

    float acc[2][NI][4];
#pragma unroll
    for (int mi = 0; mi < 2; mi++)
#pragma unroll
        for (int ni = 0; ni < NI; ni++)
#pragma unroll
            for (int q = 0; q < 4; q++) acc[mi][ni][q] = 0.0f;

    for (int cc = 0; cc <= NCHUNK; cc++) {
        if (cc < NCHUNK) {
            const int stage = cc & 1;
            const int p = cc / NK64;
            const int kk = (cc - p * NK64) * 64;
            const unsigned short* A0 = (p < 2) ? A0h : A0l;
            const unsigned short* A1 = (p < 2) ? A1h : A1l;
            const int boff = ((p == 1) ? K : 0) + kk;
            // A tile: 128 rows x 128B, swizzled
#pragma unroll
            for (int i = 0; i < 4; i++) {
                int idx = tid + i * 256;
                int r = idx >> 3, c = idx & 7;
                int rg = min(brow + r, NN - 1);
                int ke = kk + c * 8;
                const unsigned short* g =
                    (K1 == 0 || ke < K0) ? (A0 + (size_t)rg * K0 + ke)
                                         : (A1 + (size_t)rg * K1 + (ke - K0));
                cp_async16(sbase + stage * STAGE + r * 128 + ((c ^ (r & 7)) << 4), g);
            }
            // B tile: NCOL rows x 128B, swizzled
#pragma unroll
            for (int i = 0; i < (NCOL * 8) / 256; i++) {
                int idx = tid + i * 256;
                int n = idx >> 3, c = idx & 7;
                const unsigned short* g = Bp + (size_t)n * (2 * K) + boff + c * 8;
                cp_async16(sbase + stage * STAGE + ABYTES + n * 128 + ((c ^ (n & 7)) << 4), g);
            }
            asm volatile("cp.async.commit_group;");
        }
        if (cc == 0) continue;
        if (cc < NCHUNK) asm volatile("cp.async.wait_group 1;");
        else asm volatile("cp.async.wait_group 0;");
        __syncthreads();

        const int stage = (cc - 1) & 1;
        const unsigned int sA = sbase + stage * STAGE;
        const unsigned int sB = sA + ABYTES;
#pragma unroll
        for (int ks = 0; ks < 4; ks++) {
            const unsigned int coff = (unsigned int)((((ks << 1) | lhalf) ^ swz) << 4);
            unsigned int a[2][4];
#pragma unroll
            for (int mi = 0; mi < 2; mi++)
                ldsm_x4(a[mi], sA + (wr * 32 + mi * 16 + lane16) * 128 + coff);
            unsigned int b[NI][2];
#pragma unroll
            for (int nb = 0; nb < NI / 2; nb++) {
                unsigned int r4[4];
                ldsm_x4(r4, sB + (wc * WNC + nb * 16 + lane16) * 128 + coff);
                b[nb * 2][0] = r4[0];
                b[nb * 2 + 1][0] = r4[1];
                b[nb * 2][1] = r4[2];
                b[nb * 2 + 1][1] = r4[3];
            }
#pragma unroll
            for (int mi = 0; mi < 2; mi++)
#pragma unroll
                for (int ni = 0; ni < NI; ni++)
                    mma16816(acc[mi][ni], a[mi], b[ni][0], b[ni][1]);
        }
        __syncthreads();
    }

    // ---- epilogue ----
    float* sc = (float*)smem;            // [NCOL] scale
    float* sf = sc + NCOL;               // [NCOL] shift
    float* bi = sf + NCOL;               // [NCOL] bias
    if (MODE < 2) {
        if (tid < NCOL) {
            float s = gamma[tid] * rsqrtf(var[tid] + EPSB);
            sc[tid] = s;
            sf[tid] = beta[tid] - mean[tid] * s;
            bi[tid] = bias[tid];
        }
        __syncthreads();
    }

    const int g = lane >> 2, tg = lane & 3;
#pragma unroll
    for (int mi = 0; mi < 2; mi++) {
        int row0 = brow + wr * 32 + mi * 16 + g;
        int row1 = row0 + 8;
        float msk0 = 1.0f, msk1 = 1.0f;
        if (MODE == 0) {
            msk0 = (row0 < NN && invc[row0] > 0.0f) ? 1.0f : 0.0f;
            msk1 = (row1 < NN && invc[row1] > 0.0f) ? 1.0f : 0.0f;
        }
#pragma unroll
        for (int ni = 0; ni < NI; ni++) {
            int cb = wc * WNC + ni * 8 + tg * 2;
            if (MODE == 2) {
                if (row0 < NN) {
                    outF[(size_t)row0 * NCOL + cb] = fmaxf(acc[mi][ni][0] + bias[cb], 0.0f);
                    outF[(size_t)row0 * NCOL + cb + 1] = fmaxf(acc[mi][ni][1] + bias[cb + 1], 0.0f);
                }
                if (row1 < NN) {
                    outF[(size_t)row1 * NCOL + cb] = fmaxf(acc[mi][ni][2] + bias[cb], 0.0f);
                    outF[(size_t)row1 * NCOL + cb + 1] = fmaxf(acc[mi][ni][3] + bias[cb + 1], 0.0f);
                }
            } else {
                float s0 = sc[cb], s1 = sc[cb + 1];
                float f0 = sf[cb], f1 = sf[cb + 1];
                float b0 = bi[cb], b1 = bi[cb + 1];
                if (row0 < NN) {
                    float v0 = acc[mi][ni][0] + b0, v1 = acc[mi][ni][1] + b1;
                    if (MODE == 0) { v0 = fmaxf(v0, 0.f) * msk0; v1 = fmaxf(v1, 0.f) * msk0; }
                    v0 = fmaxf(s0 * v0 + f0, 0.0f);
                    v1 = fmaxf(s1 * v1 + f1, 0.0f);
                    unsigned int ph, pl;
                    split2(v0, v1, ph, pl);
                    outHi[(size_t)row0 * 64 + (cb >> 1)] = ph;
                    outLo[(size_t)row0 * 64 + (cb >> 1)] = pl;
                }
                if (row1 < NN) {
                    float v0 = acc[mi][ni][2] + b0, v1 = acc[mi][ni][3] + b1;
                    if (MODE == 0) { v0 = fmaxf(v0, 0.f) * msk1; v1 = fmaxf(v1, 0.f) * msk1; }
                    v0 = fmaxf(s0 * v0 + f0, 0.0f);
                    v1 = fmaxf(s1 * v1 + f1, 0.0f);
                    unsigned int ph, pl;
                    split2(v0, v1, ph, pl);
                    outHi[(size_t)row1 * 64 + (cb >> 1)] = ph;
                    outLo[(size_t)row1 * 64 + (cb >> 1)] = pl;
                }
            }
        }
    }
}

// final: out[i] = b5 + dot(z[i, :64], W5)
__global__ void final_kernel(const float* __restrict__ z, const float* __restrict__ W5,
                             const float* __restrict__ b5, float* __restrict__ out) {
    int i = blockIdx.x * blockDim.x + threadIdx.x;
    if (i >= NN) return;
    const float4* zr = (const float4*)(z + (size_t)i * 64);
    const float4* wr = (const float4*)W5;
    float acc = 0.0f;
#pragma unroll
    for (int j = 0; j < 16; j++) {
        float4 a = zr[j];
        float4 w = wr[j];
        acc += a.x * w.x + a.y * w.y + a.z * w.z + a.w * w.w;
    }
    out[i] = acc + b5[0];
}

// ==================== launch ====================
extern "C" void kernel_launch(void* const* d_in, const int* in_sizes, int n_in,
                              void* d_out, int out_size) {
    const float* x   = (const float*)d_in[0];
    const int*   ei0 = (const int*)d_in[1];
    const int*   ei1 = (const int*)d_in[2];
    const int*   ei2 = (const int*)d_in[3];
    const float* ea  = (const float*)d_in[4];
    const float* W1  = (const float*)d_in[5];
    const float* b1  = (const float*)d_in[6];
    const float* g1  = (const float*)d_in[7];
    const float* be1 = (const float*)d_in[8];
    const float* m1  = (const float*)d_in[9];
    const float* v1  = (const float*)d_in[10];
    const float* Wl2 = (const float*)d_in[11];
    const float* bl2 = (const float*)d_in[12];
    const float* Wr2 = (const float*)d_in[13];
    const float* g2  = (const float*)d_in[14];
    const float* be2 = (const float*)d_in[15];
    const float* m2  = (const float*)d_in[16];
    const float* v2  = (const float*)d_in[17];
    const float* Wl3 = (const float*)d_in[18];
    const float* bl3 = (const float*)d_in[19];
    const float* Wr3 = (const float*)d_in[20];
    const float* g3  = (const float*)d_in[21];
    const float* be3 = (const float*)d_in[22];
    const float* m3  = (const float*)d_in[23];
    const float* v3  = (const float*)d_in[24];
    const float* W4  = (const float*)d_in[25];
    const float* b4  = (const float*)d_in[26];
    const float* W5  = (const float*)d_in[27];
    const float* b5  = (const float*)d_in[28];
    float* out = (float*)d_out;

    unsigned int *a1h, *a1l, *aggh, *aggl, *h1h, *h1l, *h2h, *h2l, *h3h, *h3l, *xh, *xl;
    float *z, *invc;
    int *cnt, *rowptr, *cursor, *colA, *eid0;
    unsigned short *B1, *B2, *B3, *B4;
    cudaGetSymbolAddress((void**)&a1h, g_a1h);   cudaGetSymbolAddress((void**)&a1l, g_a1l);
    cudaGetSymbolAddress((void**)&aggh, g_aggh); cudaGetSymbolAddress((void**)&aggl, g_aggl);
    cudaGetSymbolAddress((void**)&h1h, g_h1h);   cudaGetSymbolAddress((void**)&h1l, g_h1l);
    cudaGetSymbolAddress((void**)&h2h, g_h2h);   cudaGetSymbolAddress((void**)&h2l, g_h2l);
    cudaGetSymbolAddress((void**)&h3h, g_h3h);   cudaGetSymbolAddress((void**)&h3l, g_h3l);
    cudaGetSymbolAddress((void**)&xh, g_xh);     cudaGetSymbolAddress((void**)&xl, g_xl);
    cudaGetSymbolAddress((void**)&z, g_z);
    cudaGetSymbolAddress((void**)&cnt, g_cnt);
    cudaGetSymbolAddress((void**)&invc, g_invc);
    cudaGetSymbolAddress((void**)&rowptr, g_rowptr);
    cudaGetSymbolAddress((void**)&cursor, g_cursor);
    cudaGetSymbolAddress((void**)&colA, g_col);
    cudaGetSymbolAddress((void**)&eid0, g_eid0);
    cudaGetSymbolAddress((void**)&B1, g_B1);
    cudaGetSymbolAddress((void**)&B2, g_B2);
    cudaGetSymbolAddress((void**)&B3, g_B3);
    cudaGetSymbolAddress((void**)&B4, g_B4);

    // dynamic smem: 2 stages x (A 16KB + B NCOL*128B)
    const int SM128 = 2 * (128 * 128 + 128 * 128);  // 65536
    const int SM64  = 2 * (128 * 128 + 64 * 128);   // 49152
    cudaFuncSetAttribute(gemm_mma<128, 0, 128, 0>,
                         cudaFuncAttributeMaxDynamicSharedMemorySize, SM128);
    cudaFuncSetAttribute(gemm_mma<128, 128, 128, 1>,
                         cudaFuncAttributeMaxDynamicSharedMemorySize, SM128);
    cudaFuncSetAttribute(gemm_mma<128, 64, 64, 2>,
                         cudaFuncAttributeMaxDynamicSharedMemorySize, SM64);

    cudaMemsetAsync(cnt, 0, 3 * NN * sizeof(int), 0);

    // B images + x split (tiny)
    prep_B<<<(128 * 128 + 255) / 256, 256>>>(W1, 96, nullptr, 0, 128, 128, B1);
    prep_B<<<(128 * 256 + 255) / 256, 256>>>(Wl2, 128, Wr2, 128, 128, 256, B2);
    prep_B<<<(128 * 256 + 255) / 256, 256>>>(Wl3, 128, Wr3, 128, 128, 256, B3);
    prep_B<<<(64 * 192 + 255) / 256, 256>>>(W4, 192, nullptr, 0, 64, 192, B4);
    prep_x<<<(NN * 32 + 255) / 256, 256>>>(x, xh, xl);

    // CSR build
    count_kernel<<<(3 * EE + 255) / 256, 256>>>(ei0, ei1, ei2, cnt);
    inv_kernel<<<(3 * NN + 255) / 256, 256>>>(cnt, invc);
    scan_kernel<<<3, 1024>>>(cnt, rowptr, cursor);
    fill_kernel<<<(EE + 255) / 256, 256>>>(ei0, cursor, colA, eid0);
    fill_kernel<<<(EE + 255) / 256, 256>>>(ei1, cursor + NN, colA + EE, nullptr);
    fill_kernel<<<(EE + 255) / 256, 256>>>(ei2, cursor + 2 * NN, colA + 2 * EE, nullptr);

    const int agg_grid = (NN + 7) / 8;
    const int G = (NN + 127) / 128;  // 391

    // conv1
    agg1_kernel<<<agg_grid, 256>>>(x, ea, rowptr, colA, eid0, invc, a1h, a1l);
    gemm_mma<128, 0, 128, 0><<<G, 256, SM128>>>(
        (unsigned short*)a1h, (unsigned short*)a1l,
        (unsigned short*)a1h, (unsigned short*)a1l,
        B1, b1, g1, be1, m1, v1, invc, h1h, h1l, nullptr);
    // conv2
    aggH_kernel<<<agg_grid, 256>>>(h1h, h1l, rowptr + (NN + 1), colA + EE, invc + NN, aggh, aggl);
    gemm_mma<128, 128, 128, 1><<<G, 256, SM128>>>(
        (unsigned short*)aggh, (unsigned short*)aggl,
        (unsigned short*)h1h, (unsigned short*)h1l,
        B2, bl2, g2, be2, m2, v2, nullptr, h2h, h2l, nullptr);
    // conv3
    aggH_kernel<<<agg_grid, 256>>>(h2h, h2l, rowptr + 2 * (NN + 1), colA + 2 * EE,
                                   invc + 2 * NN, aggh, aggl);
    gemm_mma<128, 128, 128, 1><<<G, 256, SM128>>>(
        (unsigned short*)aggh, (unsigned short*)aggl,
        (unsigned short*)h2h, (unsigned short*)h2l,
        B3, bl3, g3, be3, m3, v3, nullptr, h3h, h3l, nullptr);
    // readout MLP
    gemm_mma<128, 64, 64, 2><<<G, 256, SM64>>>(
        (unsigned short*)h3h, (unsigned short*)h3l,
        (unsigned short*)xh, (unsigned short*)xl,
        B4, b4, nullptr, nullptr, nullptr, nullptr, nullptr,
        nullptr, nullptr, z);
    final_kernel<<<(NN + 255) / 256, 256>>>(z, W5, b5, out);
}